// round 1
// baseline (speedup 1.0000x reference)
#include <cuda_runtime.h>
#include <cstdint>

#define TOPK   20
#define ROW    32000
#define ROW4   8000          // ROW / 4
#define DIM    1024
#define NB     4
#define NTOK   1024
#define NPROTO 64
#define NCHUNK 32
#define CAP    4096          // candidate buffer (32KB smem)

// -------- device scratch (no allocations allowed) --------
__device__ float g_mpn[DIM];                 // mean normalized prototype
__device__ float g_part[NB * NCHUNK * DIM];  // partial token sums
__device__ int   g_flag[NB];

// =======================================================================
// Kernel A: mean of normalized prototypes -> g_mpn  (1 block, 1024 thr)
// =======================================================================
__global__ void proto_kernel(const float* __restrict__ proto) {
    __shared__ float s_inv[NPROTO];
    int tid  = threadIdx.x;
    int lane = tid & 31;
    int w    = tid >> 5;

    // 32 warps; each warp computes norms of prototypes w and w+32
    for (int p = w; p < NPROTO; p += 32) {
        float s = 0.f;
        for (int e = lane; e < DIM; e += 32) {
            float x = proto[p * DIM + e];
            s += x * x;
        }
        #pragma unroll
        for (int o = 16; o; o >>= 1) s += __shfl_xor_sync(0xFFFFFFFFu, s, o);
        if (lane == 0) {
            float n = fmaxf(sqrtf(s), 1e-8f);
            s_inv[p] = 1.0f / (64.0f * n);
        }
    }
    __syncthreads();

    int d = tid;                       // blockDim == DIM
    float m = 0.f;
    #pragma unroll 8
    for (int p = 0; p < NPROTO; ++p) m += proto[p * DIM + d] * s_inv[p];
    g_mpn[d] = m;
}

// =======================================================================
// Kernel B1: token-chunk partial sums of hidden_states (128 blocks)
// =======================================================================
__global__ void pool_kernel(const float* __restrict__ hidden) {
    int b = blockIdx.x >> 5;           // 4 batches
    int c = blockIdx.x & 31;           // 32 chunks of 32 tokens
    int d = threadIdx.x;               // 1024 dims
    const float* p = hidden + (size_t)b * (NTOK * DIM) + (size_t)c * 32 * DIM + d;
    float s = 0.f;
    #pragma unroll
    for (int t = 0; t < 32; ++t) s += p[t * DIM];
    g_part[(b * NCHUNK + c) * DIM + d] = s;
}

// =======================================================================
// Kernel B2: flag[b] = (emb . mean_proto_n) > 0     (4 blocks, 1024 thr)
// (all positive scale factors dropped; sign is preserved)
// =======================================================================
__global__ void flag_kernel() {
    int b   = blockIdx.x;
    int tid = threadIdx.x;
    const float* pp = g_part + b * NCHUNK * DIM + tid;
    float e = 0.f;
    #pragma unroll
    for (int c = 0; c < NCHUNK; ++c) e += pp[c * DIM];
    float dot = e * g_mpn[tid];

    __shared__ float s_red[32];
    #pragma unroll
    for (int o = 16; o; o >>= 1) dot += __shfl_xor_sync(0xFFFFFFFFu, dot, o);
    if ((tid & 31) == 0) s_red[tid >> 5] = dot;
    __syncthreads();
    if (tid == 0) {
        float t = 0.f;
        #pragma unroll
        for (int i = 0; i < 32; ++i) t += s_red[i];
        g_flag[b] = (t > 0.f) ? 1 : 0;
    }
}

// =======================================================================
// Kernel C: per-row top-20 suppression + streaming copy
//           one CTA (1024 thr) per row; row lives in registers
// =======================================================================
__device__ __forceinline__ unsigned long long umax64(unsigned long long a,
                                                     unsigned long long b) {
    return a > b ? a : b;
}

__global__ __launch_bounds__(1024, 1)
void suppress_kernel(const float* __restrict__ logits, float* __restrict__ out) {
    int row = blockIdx.x;
    int b   = row >> 10;               // A=1, S=1024
    const float* src = logits + (size_t)row * ROW;
    float*       dst = out    + (size_t)row * ROW;
    int tid = threadIdx.x;

    // ---- load full row into registers (coalesced float4) ----
    float4 v[8];
    #pragma unroll
    for (int j = 0; j < 8; ++j) {
        int i4 = j * 1024 + tid;
        v[j] = (i4 < ROW4) ? ((const float4*)src)[i4]
                           : make_float4(-1e30f, -1e30f, -1e30f, -1e30f);
    }

    bool flag = (g_flag[b] != 0);

    __shared__ unsigned long long s_keys[CAP];
    __shared__ int s_cnt;
    __shared__ int s_red[32];
    __shared__ int s_top[TOPK];

    if (flag) {
        // ---- deterministic threshold ladder: first thr with count >= 20 ----
        const float cand[8] = {2.75f, 2.25f, 1.5f, 0.5f, -1.f, -4.f, -20.f, -3.0e38f};
        float thr = cand[7];
        for (int ci = 0; ci < 8; ++ci) {
            float t = cand[ci];
            int c = 0;
            #pragma unroll
            for (int j = 0; j < 8; ++j) {
                int i4 = j * 1024 + tid;
                if (i4 < ROW4) {
                    c += (v[j].x > t) + (v[j].y > t) + (v[j].z > t) + (v[j].w > t);
                }
            }
            #pragma unroll
            for (int o = 16; o; o >>= 1) c += __shfl_xor_sync(0xFFFFFFFFu, c, o);
            __syncthreads();                       // s_red reuse guard
            if ((tid & 31) == 0) s_red[tid >> 5] = c;
            __syncthreads();
            if (tid == 0) {
                int tot = 0;
                #pragma unroll
                for (int i = 0; i < 32; ++i) tot += s_red[i];
                s_cnt = tot;
            }
            __syncthreads();
            int total = s_cnt;                     // uniform across block
            if (total >= TOPK) { thr = t; break; }
        }

        // ---- gather candidates > thr as (sortable_value, ~index) keys ----
        __syncthreads();
        if (tid == 0) s_cnt = 0;
        if (tid < TOPK) s_top[tid] = 0;            // OOB safety default
        __syncthreads();
        #pragma unroll
        for (int j = 0; j < 8; ++j) {
            int i4 = j * 1024 + tid;
            if (i4 < ROW4) {
                float vv[4] = {v[j].x, v[j].y, v[j].z, v[j].w};
                #pragma unroll
                for (int cix = 0; cix < 4; ++cix) {
                    if (vv[cix] > thr) {
                        int slot = atomicAdd(&s_cnt, 1);
                        if (slot < CAP) {
                            unsigned u   = __float_as_uint(vv[cix]);
                            unsigned sbl = (u & 0x80000000u) ? ~u : (u | 0x80000000u);
                            unsigned idx = (unsigned)(i4 * 4 + cix);
                            s_keys[slot] =
                                ((unsigned long long)sbl << 32) |
                                (unsigned long long)(0xFFFFFFFFu - idx);
                        }
                    }
                }
            }
        }
        __syncthreads();
        int cnt = min(s_cnt, CAP);

        // ---- warp 0: 20 max-extractions (exact top_k tie semantics) ----
        if (tid < 32) {
            for (int t = 0; t < TOPK; ++t) {
                unsigned long long best = 0ULL;
                for (int i = tid; i < cnt; i += 32) best = umax64(best, s_keys[i]);
                #pragma unroll
                for (int o = 16; o; o >>= 1)
                    best = umax64(best, __shfl_xor_sync(0xFFFFFFFFu, best, o));
                int my = -1;
                for (int i = tid; i < cnt; i += 32)
                    if (s_keys[i] == best) { my = i; break; }
                unsigned mball = __ballot_sync(0xFFFFFFFFu, my >= 0);
                if (mball) {
                    int leader = __ffs(mball) - 1;
                    if (tid == leader) {
                        s_keys[my] = 0ULL;
                        s_top[t]   = (int)(0xFFFFFFFFu - (unsigned)best);
                    }
                }
            }
        }
        __syncthreads();
    }

    // ---- stream row back out from registers ----
    #pragma unroll
    for (int j = 0; j < 8; ++j) {
        int i4 = j * 1024 + tid;
        if (i4 < ROW4) ((float4*)dst)[i4] = v[j];
    }

    // ---- overwrite the 20 suppressed positions ----
    if (flag) {
        __syncthreads();
        if (tid < TOPK) {
            int ix = s_top[tid];
            if (ix >= 0 && ix < ROW) dst[ix] = -100.0f;
        }
    }
}

// =======================================================================
extern "C" void kernel_launch(void* const* d_in, const int* in_sizes, int n_in,
                              void* d_out, int out_size) {
    const float* proto  = (const float*)d_in[0];  // [64, 1024]
    const float* hidden = (const float*)d_in[1];  // [4, 1024, 1024]
    const float* logits = (const float*)d_in[2];  // [4, 1, 1024, 32000]
    float* out = (float*)d_out;

    proto_kernel<<<1, 1024>>>(proto);
    pool_kernel<<<NB * NCHUNK, 1024>>>(hidden);
    flag_kernel<<<NB, 1024>>>();
    suppress_kernel<<<NB * NTOK, 1024>>>(logits, out);
}

// round 2
// speedup vs baseline: 1.5545x; 1.5545x over previous
#include <cuda_runtime.h>
#include <cstdint>

#define TOPK   20
#define ROW    32000
#define ROW4   8000          // ROW / 4
#define DIM    1024
#define NB     4
#define NTOK   1024
#define NPROTO 64
#define NCHUNK 32
#define CAP    2048          // candidate buffer (16KB smem)
#define STHR   512           // suppress kernel threads

// -------- device scratch (no allocations allowed) --------
__device__ float g_mpn[DIM];                 // mean normalized prototype
__device__ float g_part[NB * NCHUNK * DIM];  // partial token sums
__device__ int   g_flag[NB];

// =======================================================================
// Kernel A: mean of normalized prototypes -> g_mpn  (1 block, 1024 thr)
// =======================================================================
__global__ void proto_kernel(const float* __restrict__ proto) {
    __shared__ float s_inv[NPROTO];
    int tid  = threadIdx.x;
    int lane = tid & 31;
    int w    = tid >> 5;

    for (int p = w; p < NPROTO; p += 32) {
        float s = 0.f;
        for (int e = lane; e < DIM; e += 32) {
            float x = proto[p * DIM + e];
            s += x * x;
        }
        #pragma unroll
        for (int o = 16; o; o >>= 1) s += __shfl_xor_sync(0xFFFFFFFFu, s, o);
        if (lane == 0) {
            float n = fmaxf(sqrtf(s), 1e-8f);
            s_inv[p] = 1.0f / (64.0f * n);
        }
    }
    __syncthreads();

    int d = tid;                       // blockDim == DIM
    float m = 0.f;
    #pragma unroll 8
    for (int p = 0; p < NPROTO; ++p) m += proto[p * DIM + d] * s_inv[p];
    g_mpn[d] = m;
}

// =======================================================================
// Kernel B1: token-chunk partial sums of hidden_states (128 blocks)
// =======================================================================
__global__ void pool_kernel(const float* __restrict__ hidden) {
    int b = blockIdx.x >> 5;           // 4 batches
    int c = blockIdx.x & 31;           // 32 chunks of 32 tokens
    int d = threadIdx.x;               // 1024 dims
    const float* p = hidden + (size_t)b * (NTOK * DIM) + (size_t)c * 32 * DIM + d;
    float s = 0.f;
    #pragma unroll
    for (int t = 0; t < 32; ++t) s += p[t * DIM];
    g_part[(b * NCHUNK + c) * DIM + d] = s;
}

// =======================================================================
// Kernel B2: flag[b] = (emb . mean_proto_n) > 0     (4 blocks, 1024 thr)
// =======================================================================
__global__ void flag_kernel() {
    int b   = blockIdx.x;
    int tid = threadIdx.x;
    const float* pp = g_part + b * NCHUNK * DIM + tid;
    float e = 0.f;
    #pragma unroll
    for (int c = 0; c < NCHUNK; ++c) e += pp[c * DIM];
    float dot = e * g_mpn[tid];

    __shared__ float s_red[32];
    #pragma unroll
    for (int o = 16; o; o >>= 1) dot += __shfl_xor_sync(0xFFFFFFFFu, dot, o);
    if ((tid & 31) == 0) s_red[tid >> 5] = dot;
    __syncthreads();
    if (tid == 0) {
        float t = 0.f;
        #pragma unroll
        for (int i = 0; i < 32; ++i) t += s_red[i];
        g_flag[b] = (t > 0.f) ? 1 : 0;
    }
}

// =======================================================================
// Kernel C: streaming copy + candidate gather + top-20 patch
//           one CTA (512 thr) per row; row is NOT retained
// =======================================================================
__device__ __forceinline__ unsigned long long umax64(unsigned long long a,
                                                     unsigned long long b) {
    return a > b ? a : b;
}

__device__ __forceinline__ unsigned long long make_key(float v, int idx) {
    unsigned u   = __float_as_uint(v);
    unsigned sbl = (u & 0x80000000u) ? ~u : (u | 0x80000000u);
    return ((unsigned long long)sbl << 32) |
           (unsigned long long)(0xFFFFFFFFu - (unsigned)idx);
}

__global__ __launch_bounds__(STHR, 3)
void suppress_kernel(const float* __restrict__ logits, float* __restrict__ out) {
    int row = blockIdx.x;
    int b   = row >> 10;               // A=1, S=1024
    const float4* __restrict__ src = (const float4*)(logits + (size_t)row * ROW);
    float4*       __restrict__ dst = (float4*)(out + (size_t)row * ROW);
    float*        dsts = out + (size_t)row * ROW;
    int tid = threadIdx.x;

    __shared__ unsigned long long s_keys[CAP];
    __shared__ int s_cnt;
    __shared__ int s_top[TOPK];

    bool flag = (g_flag[b] != 0);
    if (tid == 0) s_cnt = 0;
    if (tid < TOPK) s_top[tid] = -1;
    __syncthreads();

    const float THR0 = 2.75f;

    if (flag) {
        // ---- fused streaming copy + candidate gather ----
        #pragma unroll 4
        for (int i4 = tid; i4 < ROW4; i4 += STHR) {
            float4 v = __ldcs(&src[i4]);
            if (v.x > THR0 || v.y > THR0 || v.z > THR0 || v.w > THR0) {
                float vv[4] = {v.x, v.y, v.z, v.w};
                #pragma unroll
                for (int c = 0; c < 4; ++c) {
                    if (vv[c] > THR0) {
                        int slot = atomicAdd(&s_cnt, 1);
                        if (slot < CAP) s_keys[slot] = make_key(vv[c], i4 * 4 + c);
                    }
                }
            }
            __stcs(&dst[i4], v);
        }
        __syncthreads();
        int cnt = min(s_cnt, CAP);

        // ---- deterministic fallback (statistically never taken) ----
        if (cnt < TOPK) {
            const float ladder[6] = {2.25f, 1.5f, 0.5f, -1.f, -4.f, -3.0e38f};
            for (int li = 0; li < 6; ++li) {
                float t = ladder[li];
                __syncthreads();
                if (tid == 0) s_cnt = 0;
                __syncthreads();
                for (int i4 = tid; i4 < ROW4; i4 += STHR) {
                    float4 v = __ldcs(&src[i4]);
                    float vv[4] = {v.x, v.y, v.z, v.w};
                    #pragma unroll
                    for (int c = 0; c < 4; ++c) {
                        if (vv[c] > t) {
                            int slot = atomicAdd(&s_cnt, 1);
                            if (slot < CAP) s_keys[slot] = make_key(vv[c], i4 * 4 + c);
                        }
                    }
                }
                __syncthreads();
                cnt = min(s_cnt, CAP);
                if (cnt >= TOPK) break;
            }
        }

        // ---- warp 0: 20 max-extractions (exact top_k tie semantics) ----
        if (tid < 32) {
            for (int t = 0; t < TOPK; ++t) {
                unsigned long long best = 0ULL;
                for (int i = tid; i < cnt; i += 32) best = umax64(best, s_keys[i]);
                #pragma unroll
                for (int o = 16; o; o >>= 1)
                    best = umax64(best, __shfl_xor_sync(0xFFFFFFFFu, best, o));
                int my = -1;
                for (int i = tid; i < cnt; i += 32)
                    if (s_keys[i] == best) { my = i; break; }
                unsigned mball = __ballot_sync(0xFFFFFFFFu, my >= 0);
                if (mball) {
                    int leader = __ffs(mball) - 1;
                    if (tid == leader) {
                        s_keys[my] = 0ULL;
                        s_top[t]   = (int)(0xFFFFFFFFu - (unsigned)best);
                    }
                }
            }
        }
        __syncthreads();   // also fences the streamed global stores (block scope)

        // ---- overwrite the 20 suppressed positions ----
        if (tid < TOPK) {
            int ix = s_top[tid];
            if (ix >= 0 && ix < ROW) dsts[ix] = -100.0f;
        }
    } else {
        // ---- pure streaming copy ----
        #pragma unroll 4
        for (int i4 = tid; i4 < ROW4; i4 += STHR) {
            __stcs(&dst[i4], __ldcs(&src[i4]));
        }
    }
}

// =======================================================================
extern "C" void kernel_launch(void* const* d_in, const int* in_sizes, int n_in,
                              void* d_out, int out_size) {
    const float* proto  = (const float*)d_in[0];  // [64, 1024]
    const float* hidden = (const float*)d_in[1];  // [4, 1024, 1024]
    const float* logits = (const float*)d_in[2];  // [4, 1, 1024, 32000]
    float* out = (float*)d_out;

    proto_kernel<<<1, 1024>>>(proto);
    pool_kernel<<<NB * NCHUNK, 1024>>>(hidden);
    flag_kernel<<<NB, 1024>>>();
    suppress_kernel<<<NB * NTOK, STHR>>>(logits, out);
}

// round 3
// speedup vs baseline: 1.6782x; 1.0796x over previous
#include <cuda_runtime.h>
#include <cstdint>

#define TOPK   20
#define ROW    32000
#define ROW4   8000          // ROW / 4
#define DIM    1024
#define NB     4
#define NTOK   1024
#define NPROTO 64
#define NCHUNK 32
#define CAP    2048          // candidate buffer (16KB smem)
#define STHR   512           // suppress kernel threads
#define BATCH  6             // float4 loads in flight per thread
#define DSCALE 4294967296.0f // 2^32 fixed-point scale for the dot sign

// -------- device scratch (no allocations allowed) --------
__device__ float              g_mpn[DIM];        // mean normalized prototype
__device__ unsigned long long g_dotfix[NB];      // fixed-point emb.mpn per batch

// =======================================================================
// Kernel A: mean of normalized prototypes -> g_mpn; reset accumulators
// =======================================================================
__global__ void proto_kernel(const float* __restrict__ proto) {
    __shared__ float s_inv[NPROTO];
    int tid  = threadIdx.x;
    int lane = tid & 31;
    int w    = tid >> 5;

    if (tid < NB) g_dotfix[tid] = 0ULL;          // per-replay reset

    for (int p = w; p < NPROTO; p += 32) {
        float s = 0.f;
        for (int e = lane; e < DIM; e += 32) {
            float x = proto[p * DIM + e];
            s += x * x;
        }
        #pragma unroll
        for (int o = 16; o; o >>= 1) s += __shfl_xor_sync(0xFFFFFFFFu, s, o);
        if (lane == 0) {
            float n = fmaxf(sqrtf(s), 1e-8f);
            s_inv[p] = 1.0f / (64.0f * n);
        }
    }
    __syncthreads();

    int d = tid;                       // blockDim == DIM
    float m = 0.f;
    #pragma unroll 8
    for (int p = 0; p < NPROTO; ++p) m += proto[p * DIM + d] * s_inv[p];
    g_mpn[d] = m;
}

// =======================================================================
// Kernel B: pooled dot per chunk -> deterministic fixed-point accumulate
// (all positive scale factors of the cosine sim are dropped; sign kept)
// =======================================================================
__global__ void pool_dot_kernel(const float* __restrict__ hidden) {
    int b = blockIdx.x >> 5;           // 4 batches
    int c = blockIdx.x & 31;           // 32 chunks of 32 tokens
    int d = threadIdx.x;               // 1024 dims
    const float* p = hidden + (size_t)b * (NTOK * DIM) + (size_t)c * 32 * DIM + d;
    float s = 0.f;
    #pragma unroll
    for (int t = 0; t < 32; ++t) s += p[t * DIM];
    float dot = s * g_mpn[d];

    __shared__ float s_red[32];
    #pragma unroll
    for (int o = 16; o; o >>= 1) dot += __shfl_xor_sync(0xFFFFFFFFu, dot, o);
    if ((d & 31) == 0) s_red[d >> 5] = dot;
    __syncthreads();
    if (d == 0) {
        float t = 0.f;
        #pragma unroll
        for (int i = 0; i < 32; ++i) t += s_red[i];
        long long fx = llrintf(t * DSCALE);      // deterministic integer sum
        atomicAdd(&g_dotfix[b], (unsigned long long)fx);
    }
}

// =======================================================================
// Kernel C: streaming copy + candidate gather + top-20 patch
// =======================================================================
__device__ __forceinline__ unsigned long long umax64(unsigned long long a,
                                                     unsigned long long b) {
    return a > b ? a : b;
}

__device__ __forceinline__ unsigned long long make_key(float v, int idx) {
    unsigned u   = __float_as_uint(v);
    unsigned sbl = (u & 0x80000000u) ? ~u : (u | 0x80000000u);
    return ((unsigned long long)sbl << 32) |
           (unsigned long long)(0xFFFFFFFFu - (unsigned)idx);
}

__global__ __launch_bounds__(STHR, 3)
void suppress_kernel(const float* __restrict__ logits, float* __restrict__ out) {
    int row = blockIdx.x;
    int b   = row >> 10;               // A=1, S=1024
    const float4* __restrict__ src = (const float4*)(logits + (size_t)row * ROW);
    float4*       __restrict__ dst = (float4*)(out + (size_t)row * ROW);
    float*        dsts = out + (size_t)row * ROW;
    int tid = threadIdx.x;

    __shared__ unsigned long long s_keys[CAP];
    __shared__ int s_cnt;
    __shared__ int s_top[TOPK];

    bool flag = ((long long)g_dotfix[b] > 0LL);
    if (tid == 0) s_cnt = 0;
    if (tid < TOPK) s_top[tid] = -1;
    __syncthreads();

    const float THR0 = 2.75f;

    // ---- streaming copy with batched loads (MLP=BATCH) + gather ----
    #pragma unroll 1
    for (int base = 0; base < ROW4; base += STHR * BATCH) {
        float4 r[BATCH];
        int    ix[BATCH];
        #pragma unroll
        for (int k = 0; k < BATCH; ++k) {
            ix[k] = base + k * STHR + tid;
            r[k]  = (ix[k] < ROW4) ? __ldcs(&src[ix[k]])
                                   : make_float4(0.f, 0.f, 0.f, 0.f);
        }
        #pragma unroll
        for (int k = 0; k < BATCH; ++k) {
            if (ix[k] < ROW4) __stcs(&dst[ix[k]], r[k]);
        }
        if (flag) {
            #pragma unroll
            for (int k = 0; k < BATCH; ++k) {
                if (ix[k] < ROW4) {
                    float mx = fmaxf(fmaxf(r[k].x, r[k].y), fmaxf(r[k].z, r[k].w));
                    if (mx > THR0) {
                        float vv[4] = {r[k].x, r[k].y, r[k].z, r[k].w};
                        #pragma unroll
                        for (int c = 0; c < 4; ++c) {
                            if (vv[c] > THR0) {
                                int slot = atomicAdd(&s_cnt, 1);
                                if (slot < CAP) s_keys[slot] = make_key(vv[c], ix[k] * 4 + c);
                            }
                        }
                    }
                }
            }
        }
    }

    if (!flag) return;

    __syncthreads();
    int cnt = min(s_cnt, CAP);

    // ---- deterministic fallback (statistically never taken) ----
    if (cnt < TOPK) {
        const float ladder[6] = {2.25f, 1.5f, 0.5f, -1.f, -4.f, -3.0e38f};
        for (int li = 0; li < 6; ++li) {
            float t = ladder[li];
            __syncthreads();
            if (tid == 0) s_cnt = 0;
            __syncthreads();
            for (int i4 = tid; i4 < ROW4; i4 += STHR) {
                float4 v = __ldcs(&src[i4]);
                float vv[4] = {v.x, v.y, v.z, v.w};
                #pragma unroll
                for (int c = 0; c < 4; ++c) {
                    if (vv[c] > t) {
                        int slot = atomicAdd(&s_cnt, 1);
                        if (slot < CAP) s_keys[slot] = make_key(vv[c], i4 * 4 + c);
                    }
                }
            }
            __syncthreads();
            cnt = min(s_cnt, CAP);
            if (cnt >= TOPK) break;
        }
    }

    // ---- warp 0: 20 max-extractions (exact top_k tie semantics) ----
    if (tid < 32) {
        for (int t = 0; t < TOPK; ++t) {
            unsigned long long best = 0ULL;
            for (int i = tid; i < cnt; i += 32) best = umax64(best, s_keys[i]);
            #pragma unroll
            for (int o = 16; o; o >>= 1)
                best = umax64(best, __shfl_xor_sync(0xFFFFFFFFu, best, o));
            int my = -1;
            for (int i = tid; i < cnt; i += 32)
                if (s_keys[i] == best) { my = i; break; }
            unsigned mball = __ballot_sync(0xFFFFFFFFu, my >= 0);
            if (mball) {
                int leader = __ffs(mball) - 1;
                if (tid == leader) {
                    s_keys[my] = 0ULL;
                    s_top[t]   = (int)(0xFFFFFFFFu - (unsigned)best);
                }
            }
        }
    }
    __syncthreads();

    // ---- overwrite the 20 suppressed positions ----
    if (tid < TOPK) {
        int ix = s_top[tid];
        if (ix >= 0 && ix < ROW) dsts[ix] = -100.0f;
    }
}

// =======================================================================
extern "C" void kernel_launch(void* const* d_in, const int* in_sizes, int n_in,
                              void* d_out, int out_size) {
    const float* proto  = (const float*)d_in[0];  // [64, 1024]
    const float* hidden = (const float*)d_in[1];  // [4, 1024, 1024]
    const float* logits = (const float*)d_in[2];  // [4, 1, 1024, 32000]
    float* out = (float*)d_out;

    proto_kernel<<<1, 1024>>>(proto);
    pool_dot_kernel<<<NB * NCHUNK, 1024>>>(hidden);
    suppress_kernel<<<NB * NTOK, STHR>>>(logits, out);
}

// round 4
// speedup vs baseline: 1.7451x; 1.0398x over previous
#include <cuda_runtime.h>
#include <cstdint>

#define TOPK    20
#define ROW     32000
#define NROWS   4096
#define TOT_F4  32768000        // 4096 * 8000 float4 elements
#define DIM     1024
#define NB      4
#define NPROTO  64
#define NCHUNK  32
#define CAPC    192             // per-row candidate capacity
#define THR0    2.75f           // top-20-of-32000 N(0,1) threshold (quantile ~3.23)

// -------- device scratch (static __device__, no allocations) --------
__device__ float              g_part[NB * NCHUNK * DIM];
__device__ int                g_flag[NB];
__device__ int                g_ccnt[NROWS];
__device__ unsigned long long g_cand[NROWS * CAPC];   // ~6 MB

// =======================================================================
// helpers
// =======================================================================
__device__ __forceinline__ unsigned long long umax64(unsigned long long a,
                                                     unsigned long long b) {
    return a > b ? a : b;
}
__device__ __forceinline__ unsigned long long make_key(float v, int col) {
    unsigned u   = __float_as_uint(v);
    unsigned sbl = (u & 0x80000000u) ? ~u : (u | 0x80000000u);
    return ((unsigned long long)sbl << 32) |
           (unsigned long long)(0xFFFFFFFFu - (unsigned)col);
}

// =======================================================================
// K1: token-chunk partial sums of hidden_states (128 blocks x 1024)
//     also zeroes per-row candidate counters for this replay
// =======================================================================
__global__ void pool_kernel(const float* __restrict__ hidden) {
    int b = blockIdx.x >> 5;
    int c = blockIdx.x & 31;
    int d = threadIdx.x;
    const float* p = hidden + (size_t)b * (1024 * DIM) + (size_t)c * 32 * DIM + d;
    float s = 0.f;
    #pragma unroll
    for (int t = 0; t < 32; ++t) s += p[t * DIM];
    g_part[(b * NCHUNK + c) * DIM + d] = s;

    if (blockIdx.x < 4) g_ccnt[blockIdx.x * 1024 + d] = 0;
}

// =======================================================================
// K2: flag[b] = sign( sum_p (emb . proto_p)/max(||proto_p||,eps) ) > 0
//     (positive common factors 1/64 and 1/||emb|| dropped)
//     4 blocks x 1024 threads; deterministic reduction order
// =======================================================================
__global__ void flag_kernel(const float* __restrict__ proto) {
    __shared__ float s_emb[DIM];
    __shared__ float s_sim[32];
    int b    = blockIdx.x;
    int tid  = threadIdx.x;
    int w    = tid >> 5;
    int lane = tid & 31;

    float e = 0.f;
    #pragma unroll
    for (int c = 0; c < NCHUNK; ++c) e += g_part[(b * NCHUNK + c) * DIM + tid];
    s_emb[tid] = e;
    __syncthreads();

    float acc = 0.f;
    for (int p = w; p < NPROTO; p += 32) {
        float sq = 0.f, dt = 0.f;
        for (int d = lane; d < DIM; d += 32) {
            float x = proto[p * DIM + d];
            sq += x * x;
            dt += x * s_emb[d];
        }
        #pragma unroll
        for (int o = 16; o; o >>= 1) {
            sq += __shfl_xor_sync(0xFFFFFFFFu, sq, o);
            dt += __shfl_xor_sync(0xFFFFFFFFu, dt, o);
        }
        acc += dt / fmaxf(sqrtf(sq), 1e-8f);
    }
    if (lane == 0) s_sim[w] = acc;
    __syncthreads();
    if (tid == 0) {
        float t = 0.f;
        #pragma unroll
        for (int i = 0; i < 32; ++i) t += s_sim[i];
        g_flag[b] = (t > 0.f) ? 1 : 0;
    }
}

// =======================================================================
// K3: pure streaming copy + rare candidate append (no smem, no barriers)
//     grid 5334 x 256 threads; each CTA moves 6144 float4 (96KB)
// =======================================================================
#define C1B 6
__global__ __launch_bounds__(256, 6)
void copy_kernel(const float* __restrict__ logits, float* __restrict__ out) {
    const float4* __restrict__ src4 = (const float4*)logits;
    float4*       __restrict__ dst4 = (float4*)out;
    int tid  = threadIdx.x;
    int base = blockIdx.x * (256 * C1B * 4);

    #pragma unroll
    for (int it = 0; it < 4; ++it) {
        int b0 = base + it * (256 * C1B) + tid;
        float4 r[C1B];
        #pragma unroll
        for (int k = 0; k < C1B; ++k) {
            int ix = b0 + k * 256;
            r[k] = (ix < TOT_F4) ? __ldcs(&src4[ix])
                                 : make_float4(0.f, 0.f, 0.f, 0.f);
        }
        #pragma unroll
        for (int k = 0; k < C1B; ++k) {
            int ix = b0 + k * 256;
            if (ix < TOT_F4) __stcs(&dst4[ix], r[k]);
        }
        #pragma unroll
        for (int k = 0; k < C1B; ++k) {
            int ix = b0 + k * 256;
            if (ix < TOT_F4) {
                float mx = fmaxf(fmaxf(r[k].x, r[k].y), fmaxf(r[k].z, r[k].w));
                if (mx > THR0) {
                    float vv[4] = {r[k].x, r[k].y, r[k].z, r[k].w};
                    #pragma unroll
                    for (int c = 0; c < 4; ++c) {
                        if (vv[c] > THR0) {
                            int g   = ix * 4 + c;
                            int row = g / ROW;
                            int col = g - row * ROW;
                            int slot = atomicAdd(&g_ccnt[row], 1);
                            if (slot < CAPC)
                                g_cand[row * CAPC + slot] = make_key(vv[c], col);
                        }
                    }
                }
            }
        }
    }
}

// =======================================================================
// K4: per-row top-20 patch. One warp per row (512 blocks x 256 thr).
// =======================================================================
__global__ __launch_bounds__(256, 4)
void patch_kernel(const float* __restrict__ logits, float* __restrict__ out) {
    int w    = threadIdx.x >> 5;
    int lane = threadIdx.x & 31;
    int row  = blockIdx.x * 8 + w;
    int b    = row >> 10;
    if (!g_flag[b]) return;

    float* dst = out + (size_t)row * ROW;
    int cnt = g_ccnt[row];

    if (cnt >= TOPK && cnt <= CAPC) {
        // fast path: all candidates cached in registers (<=6 per lane)
        unsigned long long k[6];
        #pragma unroll
        for (int j = 0; j < 6; ++j) {
            int i = lane + j * 32;
            k[j] = (i < cnt) ? g_cand[row * CAPC + i] : 0ULL;
        }
        #pragma unroll 1
        for (int t = 0; t < TOPK; ++t) {
            unsigned long long best = 0ULL;
            #pragma unroll
            for (int j = 0; j < 6; ++j) best = umax64(best, k[j]);
            #pragma unroll
            for (int o = 16; o; o >>= 1)
                best = umax64(best, __shfl_xor_sync(0xFFFFFFFFu, best, o));
            #pragma unroll
            for (int j = 0; j < 6; ++j) if (k[j] == best) k[j] = 0ULL;
            unsigned col = 0xFFFFFFFFu - (unsigned)best;
            if (lane == (t & 31) && best != 0ULL && col < ROW)
                dst[col] = -100.0f;
        }
    } else {
        // deterministic slow path (statistically never taken):
        // 20 passes, monotonically descending unique keys
        const float* srcr = logits + (size_t)row * ROW;
        unsigned long long prev = ~0ULL;
        for (int t = 0; t < TOPK; ++t) {
            unsigned long long best = 0ULL;
            for (int i = lane; i < ROW; i += 32) {
                unsigned long long key = make_key(srcr[i], i);
                if (key < prev) best = umax64(best, key);
            }
            #pragma unroll
            for (int o = 16; o; o >>= 1)
                best = umax64(best, __shfl_xor_sync(0xFFFFFFFFu, best, o));
            prev = best;
            unsigned col = 0xFFFFFFFFu - (unsigned)best;
            if (lane == 0 && best != 0ULL && col < ROW)
                dst[col] = -100.0f;
        }
    }
}

// =======================================================================
extern "C" void kernel_launch(void* const* d_in, const int* in_sizes, int n_in,
                              void* d_out, int out_size) {
    const float* proto  = (const float*)d_in[0];  // [64, 1024]
    const float* hidden = (const float*)d_in[1];  // [4, 1024, 1024]
    const float* logits = (const float*)d_in[2];  // [4, 1, 1024, 32000]
    float* out = (float*)d_out;

    pool_kernel<<<128, 1024>>>(hidden);
    flag_kernel<<<NB, 1024>>>(proto);
    int grid_copy = (TOT_F4 + (256 * C1B * 4) - 1) / (256 * C1B * 4);  // 5334
    copy_kernel<<<grid_copy, 256>>>(logits, out);
    patch_kernel<<<NROWS / 8, 256>>>(logits, out);
}

// round 5
// speedup vs baseline: 1.7998x; 1.0313x over previous
#include <cuda_runtime.h>
#include <cstdint>

#define TOPK     20
#define ROW      32000
#define NROWS    4096
#define TOT_F4   32768000       // 4096 * 8000 float4 elements
#define TOT_SC   131072000      // total scalars
#define DIM      1024
#define NB       4
#define NPROTO   64
#define NCHUNK   32
#define CAPC     192            // per-row candidate capacity
#define THR0     2.75f          // top-20-of-32000 N(0,1) threshold (quantile ~3.23)
#define C1B      6              // float4 loads in flight per thread
#define CTA_F4   (256 * C1B * 4)    // 6144 float4 per CTA
#define CTA_SC   (CTA_F4 * 4)       // 24576 scalars per CTA (< ROW => <=2 rows)

// -------- device scratch (static __device__, no allocations) --------
__device__ float              g_part[NB * NCHUNK * DIM];
__device__ int                g_flag[NB];
__device__ int                g_ccnt[NROWS];
__device__ int                g_done[NROWS];
__device__ unsigned long long g_cand[NROWS * CAPC];   // ~6 MB

// =======================================================================
// helpers
// =======================================================================
__device__ __forceinline__ unsigned long long umax64(unsigned long long a,
                                                     unsigned long long b) {
    return a > b ? a : b;
}
__device__ __forceinline__ unsigned long long make_key(float v, int col) {
    unsigned u   = __float_as_uint(v);
    unsigned sbl = (u & 0x80000000u) ? ~u : (u | 0x80000000u);
    return ((unsigned long long)sbl << 32) |
           (unsigned long long)(0xFFFFFFFFu - (unsigned)col);
}

// =======================================================================
// K1: token-chunk partial sums of hidden_states (128 blocks x 1024)
//     also zeroes per-row candidate + completion counters for this replay
// =======================================================================
__global__ void pool_kernel(const float* __restrict__ hidden) {
    int b = blockIdx.x >> 5;
    int c = blockIdx.x & 31;
    int d = threadIdx.x;
    const float* p = hidden + (size_t)b * (1024 * DIM) + (size_t)c * 32 * DIM + d;
    float s = 0.f;
    #pragma unroll
    for (int t = 0; t < 32; ++t) s += p[t * DIM];
    g_part[(b * NCHUNK + c) * DIM + d] = s;

    if (blockIdx.x < 4) {
        g_ccnt[blockIdx.x * 1024 + d] = 0;
        g_done[blockIdx.x * 1024 + d] = 0;
    }
}

// =======================================================================
// K2: flag[b] = sign( sum_p (emb . proto_p)/max(||proto_p||,eps) ) > 0
//     (positive common factors 1/64 and 1/||emb|| dropped)
// =======================================================================
__global__ void flag_kernel(const float* __restrict__ proto) {
    __shared__ float s_emb[DIM];
    __shared__ float s_sim[32];
    int b    = blockIdx.x;
    int tid  = threadIdx.x;
    int w    = tid >> 5;
    int lane = tid & 31;

    float e = 0.f;
    #pragma unroll
    for (int c = 0; c < NCHUNK; ++c) e += g_part[(b * NCHUNK + c) * DIM + tid];
    s_emb[tid] = e;
    __syncthreads();

    float acc = 0.f;
    for (int p = w; p < NPROTO; p += 32) {
        float sq = 0.f, dt = 0.f;
        for (int d = lane; d < DIM; d += 32) {
            float x = proto[p * DIM + d];
            sq += x * x;
            dt += x * s_emb[d];
        }
        #pragma unroll
        for (int o = 16; o; o >>= 1) {
            sq += __shfl_xor_sync(0xFFFFFFFFu, sq, o);
            dt += __shfl_xor_sync(0xFFFFFFFFu, dt, o);
        }
        acc += dt / fmaxf(sqrtf(sq), 1e-8f);
    }
    if (lane == 0) s_sim[w] = acc;
    __syncthreads();
    if (tid == 0) {
        float t = 0.f;
        #pragma unroll
        for (int i = 0; i < 32; ++i) t += s_sim[i];
        g_flag[b] = (t > 0.f) ? 1 : 0;
    }
}

// =======================================================================
// K3: streaming copy + candidate gather + fused completion-epilogue patch
// =======================================================================
__global__ __launch_bounds__(256, 6)
void copy_kernel(const float* __restrict__ logits, float* __restrict__ out) {
    const float4* __restrict__ src4 = (const float4*)logits;
    float4*       __restrict__ dst4 = (float4*)out;
    int tid  = threadIdx.x;
    int base = blockIdx.x * CTA_F4;

    // ---- streaming main body ----
    #pragma unroll
    for (int it = 0; it < 4; ++it) {
        int b0 = base + it * (256 * C1B) + tid;
        float4 r[C1B];
        #pragma unroll
        for (int k = 0; k < C1B; ++k) {
            int ix = b0 + k * 256;
            r[k] = (ix < TOT_F4) ? __ldcs(&src4[ix])
                                 : make_float4(0.f, 0.f, 0.f, 0.f);
        }
        #pragma unroll
        for (int k = 0; k < C1B; ++k) {
            int ix = b0 + k * 256;
            if (ix < TOT_F4) __stcs(&dst4[ix], r[k]);
        }
        #pragma unroll
        for (int k = 0; k < C1B; ++k) {
            int ix = b0 + k * 256;
            if (ix < TOT_F4) {
                float mx = fmaxf(fmaxf(r[k].x, r[k].y), fmaxf(r[k].z, r[k].w));
                if (mx > THR0) {
                    float vv[4] = {r[k].x, r[k].y, r[k].z, r[k].w};
                    #pragma unroll
                    for (int c = 0; c < 4; ++c) {
                        if (vv[c] > THR0) {
                            int g   = ix * 4 + c;
                            int row = g / ROW;
                            int col = g - row * ROW;
                            int slot = atomicAdd(&g_ccnt[row], 1);
                            if (slot < CAPC)
                                g_cand[row * CAPC + slot] = make_key(vv[c], col);
                        }
                    }
                }
            }
        }
    }

    // ---- completion accounting (canonical threadfence-reduction pattern) ----
    __shared__ int s_patch[2];
    __shared__ int s_np;
    if (tid == 0) s_np = 0;
    __syncthreads();                   // all block stores/gathers done

    if (tid == 0) {
        int S0 = base * 4;
        int S1 = min(S0 + CTA_SC, TOT_SC);
        int r0 = S0 / ROW;
        int r1 = (S1 - 1) / ROW;       // r1 - r0 <= 1 since CTA_SC < ROW
        __threadfence();               // publish this block's writes
        int np = 0;
        for (int r = r0; r <= r1; ++r) {
            int a = max(S0, r * ROW);
            int e = min(S1, (r + 1) * ROW);
            int cov = e - a;
            int old = atomicAdd(&g_done[r], cov);
            if (old + cov == ROW) s_patch[np++] = r;
        }
        s_np = np;
    }
    __syncthreads();
    int np = s_np;
    if (np == 0 || tid >= 32) return;

    // ---- warp 0 patches each completed row ----
    __threadfence();                   // acquire: see other blocks' cand writes
    int lane = tid;
    for (int pi = 0; pi < np; ++pi) {
        int row = s_patch[pi];
        int b   = row >> 10;
        if (!g_flag[b]) continue;
        float* dst = out + (size_t)row * ROW;
        int cnt = g_ccnt[row];

        if (cnt >= TOPK && cnt <= CAPC) {
            // fast path: rank counting over <=192 unique keys
            const unsigned long long* cp = g_cand + (size_t)row * CAPC;
            unsigned long long mk[6];
            #pragma unroll
            for (int j = 0; j < 6; ++j) {
                int i = lane + j * 32;
                mk[j] = (i < cnt) ? cp[i] : 0ULL;
            }
            int rk[6] = {0, 0, 0, 0, 0, 0};
            #pragma unroll 4
            for (int i = 0; i < cnt; ++i) {
                unsigned long long ki = cp[i];
                #pragma unroll
                for (int j = 0; j < 6; ++j) rk[j] += (ki > mk[j]);
            }
            #pragma unroll
            for (int j = 0; j < 6; ++j) {
                int i = lane + j * 32;
                if (i < cnt && rk[j] < TOPK) {
                    unsigned col = 0xFFFFFFFFu - (unsigned)mk[j];
                    if (col < ROW) dst[col] = -100.0f;
                }
            }
        } else {
            // deterministic slow path (statistically never taken):
            // 20 passes, monotonically descending unique keys
            const float* srcr = logits + (size_t)row * ROW;
            unsigned long long prev = ~0ULL;
            for (int t = 0; t < TOPK; ++t) {
                unsigned long long best = 0ULL;
                for (int i = lane; i < ROW; i += 32) {
                    unsigned long long key = make_key(srcr[i], i);
                    if (key < prev) best = umax64(best, key);
                }
                #pragma unroll
                for (int o = 16; o; o >>= 1)
                    best = umax64(best, __shfl_xor_sync(0xFFFFFFFFu, best, o));
                prev = best;
                unsigned col = 0xFFFFFFFFu - (unsigned)best;
                if (lane == 0 && best != 0ULL && col < ROW)
                    dst[col] = -100.0f;
            }
        }
    }
}

// =======================================================================
extern "C" void kernel_launch(void* const* d_in, const int* in_sizes, int n_in,
                              void* d_out, int out_size) {
    const float* proto  = (const float*)d_in[0];  // [64, 1024]
    const float* hidden = (const float*)d_in[1];  // [4, 1024, 1024]
    const float* logits = (const float*)d_in[2];  // [4, 1, 1024, 32000]
    float* out = (float*)d_out;

    pool_kernel<<<128, 1024>>>(hidden);
    flag_kernel<<<NB, 1024>>>(proto);
    int grid_copy = (TOT_F4 + CTA_F4 - 1) / CTA_F4;   // 5334
    copy_kernel<<<grid_copy, 256>>>(logits, out);
}